// round 8
// baseline (speedup 1.0000x reference)
#include <cuda_runtime.h>
#include <cuda_bf16.h>
#include <math.h>
#include <stdint.h>

#define Bb 4
#define Cc 512
#define Nn 4096
#define GROUPS 32
#define CPG 16
#define EPS 1e-5f
#define SCALE 0.044194173824159216f  // 512^-0.5

// ---------------- scratch (device globals; no allocs allowed) ----------------
__device__ __nv_bfloat16 g_h[(size_t)Bb * Nn * Cc];     // [B][N][C]
__device__ __nv_bfloat16 g_q[(size_t)Bb * Nn * Cc];     // [B][N][C]
__device__ __nv_bfloat16 g_k[(size_t)Bb * Nn * Cc];     // [B][N][C]
__device__ __nv_bfloat16 g_v[(size_t)Bb * Cc * Nn];     // [B][C][N]
__device__ __nv_bfloat16 g_attn[(size_t)Bb * Nn * Cc];  // [B][N][C]
__device__ float         g_s[(size_t)Bb * Nn * Nn];     // [B][N][N] fp32 logits
__device__ __nv_bfloat16 g_p[(size_t)Bb * Nn * Nn];     // [B][N][N] bf16 probs
__device__ float         g_stats[Bb * GROUPS * 2];      // mean, inv per (b,g)
__device__ __nv_bfloat16 g_w4[4 * Cc * Cc];             // wq|wk|wv|wo bf16

// ---------------- helpers ----------------
__device__ __forceinline__ uint32_t smem_u32(const void* p) {
    uint32_t a;
    asm("{ .reg .u64 t; cvta.to.shared.u64 t, %1; cvt.u32.u64 %0, t; }" : "=r"(a) : "l"(p));
    return a;
}
__device__ __forceinline__ uint32_t pack_bf2(float a, float b) {
    __nv_bfloat162 t = __float22bfloat162_rn(make_float2(a, b));
    return *reinterpret_cast<uint32_t*>(&t);
}
__device__ __forceinline__ void cp_async16(uint32_t saddr, const void* gptr) {
    asm volatile("cp.async.cg.shared.global [%0], [%1], 16;" :: "r"(saddr), "l"(gptr));
}
__device__ __forceinline__ void cp_commit() {
    asm volatile("cp.async.commit_group;");
}
template<int N>
__device__ __forceinline__ void cp_wait() {
    asm volatile("cp.async.wait_group %0;" :: "n"(N));
}
__device__ __forceinline__ void ldm_x4(uint32_t& r0, uint32_t& r1, uint32_t& r2, uint32_t& r3, uint32_t addr) {
    asm volatile("ldmatrix.sync.aligned.m8n8.x4.shared.b16 {%0,%1,%2,%3}, [%4];"
                 : "=r"(r0), "=r"(r1), "=r"(r2), "=r"(r3) : "r"(addr));
}
__device__ __forceinline__ void mma_bf16(float& c0, float& c1, float& c2, float& c3,
                                         uint32_t a0, uint32_t a1, uint32_t a2, uint32_t a3,
                                         uint32_t b0, uint32_t b1) {
    asm volatile(
        "mma.sync.aligned.m16n8k16.row.col.f32.bf16.bf16.f32 "
        "{%0,%1,%2,%3}, {%4,%5,%6,%7}, {%8,%9}, {%0,%1,%2,%3};"
        : "+f"(c0), "+f"(c1), "+f"(c2), "+f"(c3)
        : "r"(a0), "r"(a1), "r"(a2), "r"(a3), "r"(b0), "r"(b1));
}

// ---------------- GroupNorm stats ----------------
__global__ __launch_bounds__(256) void gn_stats_kernel(const float* __restrict__ x, float* __restrict__ stats) {
    const int bg = blockIdx.x;
    const size_t base = (size_t)bg * CPG * Nn;
    const float* xp = x + base;
    const int total = CPG * Nn;
    float s = 0.f, ss = 0.f;
    for (int i = threadIdx.x * 4; i < total; i += 1024) {
        float4 v = *(const float4*)(xp + i);
        s += v.x + v.y + v.z + v.w;
        ss += v.x * v.x + v.y * v.y + v.z * v.z + v.w * v.w;
    }
    __shared__ float rs[256], rss[256];
    rs[threadIdx.x] = s; rss[threadIdx.x] = ss;
    __syncthreads();
    for (int o = 128; o > 0; o >>= 1) {
        if (threadIdx.x < o) { rs[threadIdx.x] += rs[threadIdx.x + o]; rss[threadIdx.x] += rss[threadIdx.x + o]; }
        __syncthreads();
    }
    if (threadIdx.x == 0) {
        float mean = rs[0] / (float)total;
        float var = rss[0] / (float)total - mean * mean;
        stats[bg * 2] = mean;
        stats[bg * 2 + 1] = rsqrtf(var + EPS);
    }
}

// ---------------- normalize + transpose: x[B,C,N] -> h[B,N,C] bf16 ----------------
__global__ __launch_bounds__(256) void gn_transpose_kernel(
    const float* __restrict__ x, const float* __restrict__ stats,
    const float* __restrict__ w, const float* __restrict__ b,
    __nv_bfloat16* __restrict__ h)
{
    const int bz = blockIdx.z;
    const int c0 = blockIdx.y * 64;
    const int n0 = blockIdx.x * 64;
    __shared__ float ts[64][65];
    const size_t xoff = (size_t)bz * Cc * Nn;
    #pragma unroll
    for (int i = 0; i < 16; i++) {
        int idx = threadIdx.x + i * 256;
        int cl = idx >> 6, nl = idx & 63;
        int c = c0 + cl;
        float mean = stats[(bz * GROUPS + (c >> 4)) * 2];
        float inv  = stats[(bz * GROUPS + (c >> 4)) * 2 + 1];
        float val = x[xoff + (size_t)c * Nn + n0 + nl];
        ts[nl][cl] = (val - mean) * inv * __ldg(w + c) + __ldg(b + c);
    }
    __syncthreads();
    const size_t hoff = (size_t)bz * Nn * Cc;
    #pragma unroll
    for (int i = 0; i < 16; i++) {
        int idx = threadIdx.x + i * 256;
        int nl = idx >> 6, cl = idx & 63;
        h[hoff + (size_t)(n0 + nl) * Cc + c0 + cl] = __float2bfloat16_rn(ts[nl][cl]);
    }
}

// ---------------- fp32 -> bf16 weight convert ----------------
__global__ __launch_bounds__(256) void cvt4_kernel(
    const float* __restrict__ w0, const float* __restrict__ w1,
    const float* __restrict__ w2, const float* __restrict__ w3,
    __nv_bfloat16* __restrict__ dst)
{
    const int which = blockIdx.y;
    const float* src = which == 0 ? w0 : which == 1 ? w1 : which == 2 ? w2 : w3;
    __nv_bfloat16* d = dst + (size_t)which * Cc * Cc;
    int i = (blockIdx.x * 256 + threadIdx.x) * 4;
    if (i < Cc * Cc) {
        float4 v = *(const float4*)(src + i);
        uint2 o;
        o.x = pack_bf2(v.x, v.y);
        o.y = pack_bf2(v.z, v.w);
        *(uint2*)((char*)d + (size_t)i * 2) = o;
    }
}

// ---------------- mma.sync bf16 GEMM:  D[M,N] = A[M,K] * B[N,K]^T ----------------
// CTA tile 128x256, BK=64 swizzled 128B rows, 3-stage cp.async, 8 warps (2Mx4N) each 64x64.
// Swizzle: 16B chunk index ^= (row & 7)  -> conflict-free cp.async stores AND ldmatrix reads.
// EPI: 0 = fp32*SCALE | 1 = bf16 + bias[col] | 2 = bf16 + bias[row]
//      3 = bf16       | 4 = fp32 + bias[row] + residual
#define BKq 64
#define STAGES 3
#define TILE_M 128
#define TILE_N 256
#define STG_A (TILE_M * BKq)                       // elems
#define STG_B (TILE_N * BKq)
#define GEMM_SMEM (STAGES * (STG_A + STG_B) * 2)   // bytes = 147456

// element offset (bf16 units) of (row r, elem c) in a swizzled [rows][64] tile
__device__ __forceinline__ uint32_t sw_idx(uint32_t r, uint32_t c) {
    uint32_t chunk = c >> 3, within = c & 7;
    return (r << 6) + (((chunk ^ (r & 7)) << 3) | within);
}

template<int EPI>
__global__ __launch_bounds__(256, 1) void gemm_mma(
    const __nv_bfloat16* __restrict__ A, size_t strA, int ldA,
    const __nv_bfloat16* __restrict__ B, size_t strB, int ldB,
    void* __restrict__ Out, size_t sOut, int ldOut,
    const float* __restrict__ bias,
    const float* __restrict__ Res, size_t sRes,
    int K)
{
    extern __shared__ __nv_bfloat16 dyn[];

    const int tid = threadIdx.x;
    const int lane = tid & 31, wid = tid >> 5;
    const int wm = (wid & 1) * 64;      // warp M offset
    const int wn = (wid >> 1) * 64;     // warp N offset
    const int bz = blockIdx.z;

    const __nv_bfloat16* Ab = A + bz * strA + (size_t)(blockIdx.y * TILE_M) * ldA;
    const __nv_bfloat16* Bp = B + bz * strB + (size_t)(blockIdx.x * TILE_N) * ldB;

    auto load_chunk = [&](int chunk, int buf) {
        const int k0 = chunk * BKq;
        __nv_bfloat16* baseA = dyn + (size_t)buf * STG_A;
        __nv_bfloat16* baseB = dyn + (size_t)STAGES * STG_A + (size_t)buf * STG_B;
        #pragma unroll
        for (int j = 0; j < 4; j++) {    // A: 128 rows x 8 chunks = 1024 / 256 thr
            int idx = tid + j * 256;
            int r = idx >> 3, ck = idx & 7;
            cp_async16(smem_u32(baseA + sw_idx(r, ck * 8)), Ab + (size_t)r * ldA + k0 + ck * 8);
        }
        #pragma unroll
        for (int j = 0; j < 8; j++) {    // B: 256 rows x 8 chunks = 2048 / 256 thr
            int idx = tid + j * 256;
            int r = idx >> 3, ck = idx & 7;
            cp_async16(smem_u32(baseB + sw_idx(r, ck * 8)), Bp + (size_t)r * ldB + k0 + ck * 8);
        }
        cp_commit();
    };

    float acc[4][8][4];
    #pragma unroll
    for (int i = 0; i < 4; i++)
        #pragma unroll
        for (int j = 0; j < 8; j++)
            #pragma unroll
            for (int t = 0; t < 4; t++) acc[i][j][t] = 0.f;

    const int nc = K / BKq;
    #pragma unroll
    for (int s = 0; s < STAGES - 1; s++) load_chunk(s, s);

    for (int i = 0; i < nc; i++) {
        cp_wait<STAGES - 2>();
        __syncthreads();
        const int buf = i % STAGES;
        const uint32_t sAb = smem_u32(dyn + (size_t)buf * STG_A);
        const uint32_t sBb = smem_u32(dyn + (size_t)STAGES * STG_A + (size_t)buf * STG_B);

        #pragma unroll
        for (int ks = 0; ks < 4; ks++) {
            const uint32_t cb = ks * 2 + (lane >> 4);   // 16B chunk index (0..7)
            uint32_t a[4][4];
            #pragma unroll
            for (int mt = 0; mt < 4; mt++) {
                uint32_t r = wm + mt * 16 + (lane & 15);
                ldm_x4(a[mt][0], a[mt][1], a[mt][2], a[mt][3], sAb + (sw_idx(r, cb << 3) << 1));
            }
            uint32_t br[4][4];
            #pragma unroll
            for (int ntp = 0; ntp < 4; ntp++) {
                uint32_t r = wn + ntp * 16 + (lane & 15);
                ldm_x4(br[ntp][0], br[ntp][1], br[ntp][2], br[ntp][3], sBb + (sw_idx(r, cb << 3) << 1));
            }
            #pragma unroll
            for (int mt = 0; mt < 4; mt++)
                #pragma unroll
                for (int nt = 0; nt < 8; nt++) {
                    int ntp = nt >> 1, sel = nt & 1;
                    mma_bf16(acc[mt][nt][0], acc[mt][nt][1], acc[mt][nt][2], acc[mt][nt][3],
                             a[mt][0], a[mt][1], a[mt][2], a[mt][3],
                             br[ntp][sel], br[ntp][sel + 2]);
                }
        }
        __syncthreads();
        if (i + STAGES - 1 < nc) load_chunk(i + STAGES - 1, (i + STAGES - 1) % STAGES);
        else cp_commit();
    }

    // -------- epilogue --------
    const int rbase = blockIdx.y * TILE_M + wm + (lane >> 2);
    const int cbase = blockIdx.x * TILE_N + wn + ((lane & 3) << 1);

    #pragma unroll
    for (int mt = 0; mt < 4; mt++) {
        #pragma unroll
        for (int half = 0; half < 2; half++) {
            const int row = rbase + mt * 16 + half * 8;
            float brow = (EPI == 2 || EPI == 4) ? __ldg(bias + row) : 0.f;
            #pragma unroll
            for (int nt = 0; nt < 8; nt++) {
                const int col = cbase + nt * 8;
                float v0 = acc[mt][nt][half * 2 + 0];
                float v1 = acc[mt][nt][half * 2 + 1];
                if (EPI == 0) {
                    float* op = (float*)Out + bz * sOut + (size_t)row * ldOut + col;
                    *(float2*)op = make_float2(v0 * SCALE, v1 * SCALE);
                } else if (EPI == 4) {
                    const float* rp = Res + bz * sRes + (size_t)row * ldOut + col;
                    float2 rv = *(const float2*)rp;
                    float* op = (float*)Out + bz * sOut + (size_t)row * ldOut + col;
                    *(float2*)op = make_float2(v0 + brow + rv.x, v1 + brow + rv.y);
                } else {
                    float b0 = 0.f, b1 = 0.f;
                    if (EPI == 1) { b0 = __ldg(bias + col); b1 = __ldg(bias + col + 1); }
                    else if (EPI == 2) { b0 = brow; b1 = brow; }
                    __nv_bfloat16* op = (__nv_bfloat16*)Out + bz * sOut + (size_t)row * ldOut + col;
                    *(uint32_t*)op = pack_bf2(v0 + b0, v1 + b1);
                }
            }
        }
    }
}

// ---------------- softmax: fp32 S rows -> bf16 P ----------------
__global__ __launch_bounds__(256) void softmax_kernel(const float* __restrict__ S, __nv_bfloat16* __restrict__ P) {
    const size_t base = (size_t)blockIdx.x * Nn;
    const float* Sr = S + base;
    const int tid = threadIdx.x;
    float v[16];
    #pragma unroll
    for (int ch = 0; ch < 4; ch++) {
        float4 f = *(const float4*)(Sr + tid * 4 + ch * 1024);
        v[ch * 4] = f.x; v[ch * 4 + 1] = f.y; v[ch * 4 + 2] = f.z; v[ch * 4 + 3] = f.w;
    }
    float m = v[0];
    #pragma unroll
    for (int j = 1; j < 16; j++) m = fmaxf(m, v[j]);
    #pragma unroll
    for (int o = 16; o > 0; o >>= 1) m = fmaxf(m, __shfl_xor_sync(0xFFFFFFFFu, m, o));
    __shared__ float red[8];
    if ((tid & 31) == 0) red[tid >> 5] = m;
    __syncthreads();
    if (tid < 8) {
        float t = red[tid];
        #pragma unroll
        for (int o = 4; o > 0; o >>= 1) t = fmaxf(t, __shfl_xor_sync(0xFFu, t, o));
        red[tid] = t;
    }
    __syncthreads();
    m = red[0];
    float s = 0.f;
    #pragma unroll
    for (int j = 0; j < 16; j++) { v[j] = __expf(v[j] - m); s += v[j]; }
    #pragma unroll
    for (int o = 16; o > 0; o >>= 1) s += __shfl_xor_sync(0xFFFFFFFFu, s, o);
    __shared__ float red2[8];
    if ((tid & 31) == 0) red2[tid >> 5] = s;
    __syncthreads();
    if (tid < 8) {
        float t = red2[tid];
        #pragma unroll
        for (int o = 4; o > 0; o >>= 1) t += __shfl_xor_sync(0xFFu, t, o);
        red2[tid] = t;
    }
    __syncthreads();
    const float inv = 1.0f / red2[0];
    __nv_bfloat16* Pr = P + base;
    #pragma unroll
    for (int ch = 0; ch < 4; ch++) {
        uint2 u;
        u.x = pack_bf2(v[ch * 4] * inv, v[ch * 4 + 1] * inv);
        u.y = pack_bf2(v[ch * 4 + 2] * inv, v[ch * 4 + 3] * inv);
        *(uint2*)(Pr + tid * 4 + ch * 1024) = u;
    }
}

// ---------------- launch ----------------
extern "C" void kernel_launch(void* const* d_in, const int* in_sizes, int n_in,
                              void* d_out, int out_size)
{
    const float* x    = (const float*)d_in[0];
    const float* gn_w = (const float*)d_in[1];
    const float* gn_b = (const float*)d_in[2];
    const float* wq   = (const float*)d_in[3];
    const float* bq   = (const float*)d_in[4];
    const float* wk   = (const float*)d_in[5];
    const float* bk   = (const float*)d_in[6];
    const float* wv   = (const float*)d_in[7];
    const float* bv   = (const float*)d_in[8];
    const float* wo   = (const float*)d_in[9];
    const float* bo   = (const float*)d_in[10];
    float* out = (float*)d_out;

    __nv_bfloat16 *h, *q, *k, *v, *attn, *p, *w4;
    float *s, *stats;
    cudaGetSymbolAddress((void**)&h, g_h);
    cudaGetSymbolAddress((void**)&q, g_q);
    cudaGetSymbolAddress((void**)&k, g_k);
    cudaGetSymbolAddress((void**)&v, g_v);
    cudaGetSymbolAddress((void**)&attn, g_attn);
    cudaGetSymbolAddress((void**)&s, g_s);
    cudaGetSymbolAddress((void**)&p, g_p);
    cudaGetSymbolAddress((void**)&stats, g_stats);
    cudaGetSymbolAddress((void**)&w4, g_w4);
    __nv_bfloat16* bwq = w4;
    __nv_bfloat16* bwk = w4 + (size_t)Cc * Cc;
    __nv_bfloat16* bwv = w4 + (size_t)2 * Cc * Cc;
    __nv_bfloat16* bwo = w4 + (size_t)3 * Cc * Cc;

    cudaFuncSetAttribute(gemm_mma<0>, cudaFuncAttributeMaxDynamicSharedMemorySize, GEMM_SMEM);
    cudaFuncSetAttribute(gemm_mma<1>, cudaFuncAttributeMaxDynamicSharedMemorySize, GEMM_SMEM);
    cudaFuncSetAttribute(gemm_mma<2>, cudaFuncAttributeMaxDynamicSharedMemorySize, GEMM_SMEM);
    cudaFuncSetAttribute(gemm_mma<3>, cudaFuncAttributeMaxDynamicSharedMemorySize, GEMM_SMEM);
    cudaFuncSetAttribute(gemm_mma<4>, cudaFuncAttributeMaxDynamicSharedMemorySize, GEMM_SMEM);

    cvt4_kernel<<<dim3(Cc * Cc / 1024, 4), 256>>>(wq, wk, wv, wo, w4);

    gn_stats_kernel<<<Bb * GROUPS, 256>>>(x, stats);
    gn_transpose_kernel<<<dim3(Nn / 64, Cc / 64, Bb), 256>>>(x, stats, gn_w, gn_b, h);

    const size_t sNC = (size_t)Nn * Cc;
    const size_t sCN = (size_t)Cc * Nn;
    const size_t sNN = (size_t)Nn * Nn;

    // q,k: D[n][o] = h[n,:] . wq[o,:] -> bf16 [N,C], bias over cols
    gemm_mma<1><<<dim3(Cc / TILE_N, Nn / TILE_M, Bb), 256, GEMM_SMEM>>>(
        h, sNC, Cc, bwq, 0, Cc, q, sNC, Cc, bq, nullptr, 0, Cc);
    gemm_mma<1><<<dim3(Cc / TILE_N, Nn / TILE_M, Bb), 256, GEMM_SMEM>>>(
        h, sNC, Cc, bwk, 0, Cc, k, sNC, Cc, bk, nullptr, 0, Cc);
    // v: D[o][n] = wv[o,:] . h[n,:] -> bf16 [C,N], bias over rows
    gemm_mma<2><<<dim3(Nn / TILE_N, Cc / TILE_M, Bb), 256, GEMM_SMEM>>>(
        bwv, 0, Cc, h, sNC, Cc, v, sCN, Nn, bv, nullptr, 0, Cc);
    // S: D[n][m] = q[n,:] . k[m,:] * scale -> fp32 [N,N]
    gemm_mma<0><<<dim3(Nn / TILE_N, Nn / TILE_M, Bb), 256, GEMM_SMEM>>>(
        q, sNC, Cc, k, sNC, Cc, s, sNN, Nn, nullptr, nullptr, 0, Cc);

    softmax_kernel<<<Bb * Nn, 256>>>(s, p);

    // attn: D[n][c] = P[n,:] . v[c,:] -> bf16 [N,C]
    gemm_mma<3><<<dim3(Cc / TILE_N, Nn / TILE_M, Bb), 256, GEMM_SMEM>>>(
        p, sNN, Nn, v, sCN, Nn, attn, sNC, Cc, nullptr, nullptr, 0, Nn);
    // out: D[o][n] = wo[o,:] . attn[n,:] + bo + x -> fp32 [C,N]
    gemm_mma<4><<<dim3(Nn / TILE_N, Cc / TILE_M, Bb), 256, GEMM_SMEM>>>(
        bwo, 0, Cc, attn, sNC, Cc, out, sCN, Nn, bo, x, sCN, Cc);
}

// round 11
// speedup vs baseline: 1.1387x; 1.1387x over previous
#include <cuda_runtime.h>
#include <cuda_bf16.h>
#include <math.h>
#include <stdint.h>

#define Bb 4
#define Cc 512
#define Nn 4096
#define GROUPS 32
#define CPG 16
#define EPS 1e-5f
#define SCALE 0.044194173824159216f  // 512^-0.5

// ---------------- scratch (device globals; no allocs allowed) ----------------
__device__ __nv_bfloat16 g_h[(size_t)Bb * Nn * Cc];     // [B][N][C]
__device__ __nv_bfloat16 g_q[(size_t)Bb * Nn * Cc];     // [B][N][C]
__device__ __nv_bfloat16 g_k[(size_t)Bb * Nn * Cc];     // [B][N][C]
__device__ __nv_bfloat16 g_v[(size_t)Bb * Cc * Nn];     // [B][C][N]
__device__ __nv_bfloat16 g_attn[(size_t)Bb * Nn * Cc];  // [B][N][C]
__device__ __nv_bfloat16 g_p[(size_t)Bb * Nn * Nn];     // [B][N][N] bf16 exp(logits)
__device__ float         g_part[(size_t)Bb * Nn * 32];  // per-(row, col-tile) exp partial sums
__device__ float         g_rsum[Bb * Nn];               // softmax denominators
__device__ float         g_stats[Bb * GROUPS * 2];      // mean, inv per (b,g)
__device__ __nv_bfloat16 g_w4[4 * Cc * Cc];             // wq|wk|wv|wo bf16

// ---------------- helpers ----------------
__device__ __forceinline__ uint32_t smem_u32(const void* p) {
    uint32_t a;
    asm("{ .reg .u64 t; cvta.to.shared.u64 t, %1; cvt.u32.u64 %0, t; }" : "=r"(a) : "l"(p));
    return a;
}
__device__ __forceinline__ uint32_t pack_bf2(float a, float b) {
    __nv_bfloat162 t = __float22bfloat162_rn(make_float2(a, b));
    return *reinterpret_cast<uint32_t*>(&t);
}
__device__ __forceinline__ void cp_async16(uint32_t saddr, const void* gptr) {
    asm volatile("cp.async.cg.shared.global [%0], [%1], 16;" :: "r"(saddr), "l"(gptr));
}
__device__ __forceinline__ void cp_commit() {
    asm volatile("cp.async.commit_group;");
}
template<int N>
__device__ __forceinline__ void cp_wait() {
    asm volatile("cp.async.wait_group %0;" :: "n"(N));
}
__device__ __forceinline__ void ldm_x4(uint32_t& r0, uint32_t& r1, uint32_t& r2, uint32_t& r3, uint32_t addr) {
    asm volatile("ldmatrix.sync.aligned.m8n8.x4.shared.b16 {%0,%1,%2,%3}, [%4];"
                 : "=r"(r0), "=r"(r1), "=r"(r2), "=r"(r3) : "r"(addr));
}
__device__ __forceinline__ void mma_bf16(float& c0, float& c1, float& c2, float& c3,
                                         uint32_t a0, uint32_t a1, uint32_t a2, uint32_t a3,
                                         uint32_t b0, uint32_t b1) {
    asm volatile(
        "mma.sync.aligned.m16n8k16.row.col.f32.bf16.bf16.f32 "
        "{%0,%1,%2,%3}, {%4,%5,%6,%7}, {%8,%9}, {%0,%1,%2,%3};"
        : "+f"(c0), "+f"(c1), "+f"(c2), "+f"(c3)
        : "r"(a0), "r"(a1), "r"(a2), "r"(a3), "r"(b0), "r"(b1));
}

// ---------------- GroupNorm stats ----------------
__global__ __launch_bounds__(256) void gn_stats_kernel(const float* __restrict__ x, float* __restrict__ stats) {
    const int bg = blockIdx.x;
    const size_t base = (size_t)bg * CPG * Nn;
    const float* xp = x + base;
    const int total = CPG * Nn;
    float s = 0.f, ss = 0.f;
    for (int i = threadIdx.x * 4; i < total; i += 1024) {
        float4 v = *(const float4*)(xp + i);
        s += v.x + v.y + v.z + v.w;
        ss += v.x * v.x + v.y * v.y + v.z * v.z + v.w * v.w;
    }
    __shared__ float rs[256], rss[256];
    rs[threadIdx.x] = s; rss[threadIdx.x] = ss;
    __syncthreads();
    for (int o = 128; o > 0; o >>= 1) {
        if (threadIdx.x < o) { rs[threadIdx.x] += rs[threadIdx.x + o]; rss[threadIdx.x] += rss[threadIdx.x + o]; }
        __syncthreads();
    }
    if (threadIdx.x == 0) {
        float mean = rs[0] / (float)total;
        float var = rss[0] / (float)total - mean * mean;
        stats[bg * 2] = mean;
        stats[bg * 2 + 1] = rsqrtf(var + EPS);
    }
}

// ---------------- normalize + transpose: x[B,C,N] -> h[B,N,C] bf16 ----------------
__global__ __launch_bounds__(256) void gn_transpose_kernel(
    const float* __restrict__ x, const float* __restrict__ stats,
    const float* __restrict__ w, const float* __restrict__ b,
    __nv_bfloat16* __restrict__ h)
{
    const int bz = blockIdx.z;
    const int c0 = blockIdx.y * 64;
    const int n0 = blockIdx.x * 64;
    __shared__ float ts[64][65];
    const size_t xoff = (size_t)bz * Cc * Nn;
    #pragma unroll
    for (int i = 0; i < 16; i++) {
        int idx = threadIdx.x + i * 256;
        int cl = idx >> 6, nl = idx & 63;
        int c = c0 + cl;
        float mean = stats[(bz * GROUPS + (c >> 4)) * 2];
        float inv  = stats[(bz * GROUPS + (c >> 4)) * 2 + 1];
        float val = x[xoff + (size_t)c * Nn + n0 + nl];
        ts[nl][cl] = (val - mean) * inv * __ldg(w + c) + __ldg(b + c);
    }
    __syncthreads();
    const size_t hoff = (size_t)bz * Nn * Cc;
    #pragma unroll
    for (int i = 0; i < 16; i++) {
        int idx = threadIdx.x + i * 256;
        int nl = idx >> 6, cl = idx & 63;
        h[hoff + (size_t)(n0 + nl) * Cc + c0 + cl] = __float2bfloat16_rn(ts[nl][cl]);
    }
}

// ---------------- fp32 -> bf16 weight convert ----------------
__global__ __launch_bounds__(256) void cvt4_kernel(
    const float* __restrict__ w0, const float* __restrict__ w1,
    const float* __restrict__ w2, const float* __restrict__ w3,
    __nv_bfloat16* __restrict__ dst)
{
    const int which = blockIdx.y;
    const float* src = which == 0 ? w0 : which == 1 ? w1 : which == 2 ? w2 : w3;
    __nv_bfloat16* d = dst + (size_t)which * Cc * Cc;
    int i = (blockIdx.x * 256 + threadIdx.x) * 4;
    if (i < Cc * Cc) {
        float4 v = *(const float4*)(src + i);
        uint2 o;
        o.x = pack_bf2(v.x, v.y);
        o.y = pack_bf2(v.z, v.w);
        *(uint2*)((char*)d + (size_t)i * 2) = o;
    }
}

// ---------------- rowsum reduce: 32 partials per row -> denominator ----------------
__global__ __launch_bounds__(256) void rowsum_kernel(const float* __restrict__ part, float* __restrict__ rsum) {
    int i = blockIdx.x * 256 + threadIdx.x;
    if (i < Bb * Nn) {
        const float* p = part + (size_t)i * 32;
        float s = 0.f;
        #pragma unroll
        for (int j = 0; j < 32; j++) s += p[j];
        rsum[i] = s;
    }
}

// ---------------- mma.sync bf16 GEMM:  D[M,N] = A[M,K] * B[N,K]^T ----------------
// CTA tile 128x128, BK=64 (128B swizzled rows), 3-stage cp.async, 8 warps (2x4) each 64x32.
// Mainloop identical to the proven R5 engine (double barrier).
// EPI: 0 = exp(acc*SCALE) -> bf16 E + deterministic row partial sums
//      1 = bf16 + bias[col] | 2 = bf16 + bias[row]
//      4 = fp32 + bias[row] + residual | 5 = bf16 * (1/rowsum[row])
#define BKq 64
#define STAGES 3
#define TILE_M 128
#define TILE_N 128
#define STG_ELEMS (TILE_M * BKq)
#define GEMM_SMEM (STAGES * 2 * STG_ELEMS * 2)   // 98304 bytes

// element offset (bf16 units) of (row r, elem c) in a swizzled [128][64] tile
__device__ __forceinline__ uint32_t sw_idx(uint32_t r, uint32_t c) {
    uint32_t chunk = c >> 3, within = c & 7;
    return (r << 6) + (((chunk ^ (r & 7)) << 3) | within);
}

template<int EPI>
__global__ __launch_bounds__(256, 2) void gemm_mma(
    const __nv_bfloat16* __restrict__ A, size_t strA, int ldA,
    const __nv_bfloat16* __restrict__ B, size_t strB, int ldB,
    void* __restrict__ Out, size_t sOut, int ldOut,
    const float* __restrict__ bias,
    const float* __restrict__ Aux, size_t sAux,   // EPI0: partials | EPI4: residual | EPI5: rowsum
    int K)
{
    extern __shared__ __nv_bfloat16 dyn[];

    const int tid = threadIdx.x;
    const int lane = tid & 31, wid = tid >> 5;
    const int wm = (wid & 1) * 64;      // warp M offset
    const int wn = (wid >> 1) * 32;     // warp N offset
    const int bz = blockIdx.z;

    const __nv_bfloat16* Ab = A + bz * strA + (size_t)(blockIdx.y * TILE_M) * ldA;
    const __nv_bfloat16* Bp = B + bz * strB + (size_t)(blockIdx.x * TILE_N) * ldB;

    auto load_chunk = [&](int chunk, int buf) {
        const int k0 = chunk * BKq;
        __nv_bfloat16* baseA = dyn + (size_t)buf * STG_ELEMS;
        __nv_bfloat16* baseB = dyn + (size_t)(STAGES + buf) * STG_ELEMS;
        #pragma unroll
        for (int j = 0; j < 4; j++) {
            int idx = tid + j * 256;
            int r = idx >> 3, ck = idx & 7;
            cp_async16(smem_u32(baseA + sw_idx(r, ck * 8)), Ab + (size_t)r * ldA + k0 + ck * 8);
        }
        #pragma unroll
        for (int j = 0; j < 4; j++) {
            int idx = tid + j * 256;
            int r = idx >> 3, ck = idx & 7;
            cp_async16(smem_u32(baseB + sw_idx(r, ck * 8)), Bp + (size_t)r * ldB + k0 + ck * 8);
        }
        cp_commit();
    };

    float acc[4][4][4];
    #pragma unroll
    for (int i = 0; i < 4; i++)
        #pragma unroll
        for (int j = 0; j < 4; j++)
            #pragma unroll
            for (int t = 0; t < 4; t++) acc[i][j][t] = 0.f;

    const int nc = K / BKq;
    #pragma unroll
    for (int s = 0; s < STAGES - 1; s++) load_chunk(s, s);

    for (int i = 0; i < nc; i++) {
        cp_wait<STAGES - 2>();
        __syncthreads();
        const int buf = i % STAGES;
        const uint32_t sAb = smem_u32(dyn + (size_t)buf * STG_ELEMS);
        const uint32_t sBb = smem_u32(dyn + (size_t)(STAGES + buf) * STG_ELEMS);

        #pragma unroll
        for (int ks = 0; ks < 4; ks++) {
            const uint32_t cb = ks * 2 + (lane >> 4);   // 16B chunk index (0..7)
            uint32_t a[4][4];
            #pragma unroll
            for (int mt = 0; mt < 4; mt++) {
                uint32_t r = wm + mt * 16 + (lane & 15);
                ldm_x4(a[mt][0], a[mt][1], a[mt][2], a[mt][3], sAb + (sw_idx(r, cb << 3) << 1));
            }
            uint32_t br[2][4];
            #pragma unroll
            for (int ntp = 0; ntp < 2; ntp++) {
                uint32_t r = wn + ntp * 16 + (lane & 15);
                ldm_x4(br[ntp][0], br[ntp][1], br[ntp][2], br[ntp][3], sBb + (sw_idx(r, cb << 3) << 1));
            }
            #pragma unroll
            for (int mt = 0; mt < 4; mt++)
                #pragma unroll
                for (int nt = 0; nt < 4; nt++) {
                    int ntp = nt >> 1, sel = nt & 1;
                    mma_bf16(acc[mt][nt][0], acc[mt][nt][1], acc[mt][nt][2], acc[mt][nt][3],
                             a[mt][0], a[mt][1], a[mt][2], a[mt][3],
                             br[ntp][sel], br[ntp][sel + 2]);
                }
        }
        __syncthreads();
        if (i + STAGES - 1 < nc) load_chunk(i + STAGES - 1, (i + STAGES - 1) % STAGES);
        else cp_commit();
    }

    // -------- epilogue --------
    const int rbase = blockIdx.y * TILE_M + wm + (lane >> 2);
    const int cbase = blockIdx.x * TILE_N + wn + ((lane & 3) << 1);

    float rsum8[8];
    #pragma unroll
    for (int t = 0; t < 8; t++) rsum8[t] = 0.f;

    #pragma unroll
    for (int mt = 0; mt < 4; mt++) {
        #pragma unroll
        for (int half = 0; half < 2; half++) {
            const int row = rbase + mt * 16 + half * 8;
            float brow = (EPI == 2 || EPI == 4) ? __ldg(bias + row) : 0.f;
            float inv = 1.f;
            if (EPI == 5) inv = 1.0f / __ldg(Aux + (size_t)bz * sAux + row);
            #pragma unroll
            for (int nt = 0; nt < 4; nt++) {
                const int col = cbase + nt * 8;
                float v0 = acc[mt][nt][half * 2 + 0];
                float v1 = acc[mt][nt][half * 2 + 1];
                if (EPI == 0) {
                    float e0 = __expf(v0 * SCALE);
                    float e1 = __expf(v1 * SCALE);
                    rsum8[mt * 2 + half] += e0 + e1;
                    __nv_bfloat16* op = (__nv_bfloat16*)Out + bz * sOut + (size_t)row * ldOut + col;
                    *(uint32_t*)op = pack_bf2(e0, e1);
                } else if (EPI == 4) {
                    const float* rp = Aux + bz * sAux + (size_t)row * ldOut + col;
                    float2 rv = *(const float2*)rp;
                    float* op = (float*)Out + bz * sOut + (size_t)row * ldOut + col;
                    *(float2*)op = make_float2(v0 + brow + rv.x, v1 + brow + rv.y);
                } else if (EPI == 5) {
                    __nv_bfloat16* op = (__nv_bfloat16*)Out + bz * sOut + (size_t)row * ldOut + col;
                    *(uint32_t*)op = pack_bf2(v0 * inv, v1 * inv);
                } else {
                    float b0 = 0.f, b1 = 0.f;
                    if (EPI == 1) { b0 = __ldg(bias + col); b1 = __ldg(bias + col + 1); }
                    else if (EPI == 2) { b0 = brow; b1 = brow; }
                    __nv_bfloat16* op = (__nv_bfloat16*)Out + bz * sOut + (size_t)row * ldOut + col;
                    *(uint32_t*)op = pack_bf2(v0 + b0, v1 + b1);
                }
            }
        }
    }

    if (EPI == 0) {
        // deterministic per-row partial sums: quad shuffle -> smem cross-warp -> global
        float (*srs)[4] = (float (*)[4])dyn;
        __syncthreads();   // mainloop smem reads complete before reuse
        #pragma unroll
        for (int t = 0; t < 8; t++) {
            float r = rsum8[t];
            r += __shfl_xor_sync(0xFFFFFFFFu, r, 1);
            r += __shfl_xor_sync(0xFFFFFFFFu, r, 2);
            if ((lane & 3) == 0) {
                int mt = t >> 1, half = t & 1;
                int lrow = wm + mt * 16 + half * 8 + (lane >> 2);
                srs[lrow][wid >> 1] = r;
            }
        }
        __syncthreads();
        if (tid < 128) {
            float s = srs[tid][0] + srs[tid][1] + srs[tid][2] + srs[tid][3];
            float* part = (float*)Aux;
            part[((size_t)bz * Nn + blockIdx.y * TILE_M + tid) * 32 + blockIdx.x] = s;
        }
    }
}

// ---------------- launch ----------------
extern "C" void kernel_launch(void* const* d_in, const int* in_sizes, int n_in,
                              void* d_out, int out_size)
{
    const float* x    = (const float*)d_in[0];
    const float* gn_w = (const float*)d_in[1];
    const float* gn_b = (const float*)d_in[2];
    const float* wq   = (const float*)d_in[3];
    const float* bq   = (const float*)d_in[4];
    const float* wk   = (const float*)d_in[5];
    const float* bk   = (const float*)d_in[6];
    const float* wv   = (const float*)d_in[7];
    const float* bv   = (const float*)d_in[8];
    const float* wo   = (const float*)d_in[9];
    const float* bo   = (const float*)d_in[10];
    float* out = (float*)d_out;

    __nv_bfloat16 *h, *q, *k, *v, *attn, *p, *w4;
    float *stats, *part, *rsum;
    cudaGetSymbolAddress((void**)&h, g_h);
    cudaGetSymbolAddress((void**)&q, g_q);
    cudaGetSymbolAddress((void**)&k, g_k);
    cudaGetSymbolAddress((void**)&v, g_v);
    cudaGetSymbolAddress((void**)&attn, g_attn);
    cudaGetSymbolAddress((void**)&p, g_p);
    cudaGetSymbolAddress((void**)&stats, g_stats);
    cudaGetSymbolAddress((void**)&part, g_part);
    cudaGetSymbolAddress((void**)&rsum, g_rsum);
    cudaGetSymbolAddress((void**)&w4, g_w4);
    __nv_bfloat16* bwq = w4;
    __nv_bfloat16* bwk = w4 + (size_t)Cc * Cc;
    __nv_bfloat16* bwv = w4 + (size_t)2 * Cc * Cc;
    __nv_bfloat16* bwo = w4 + (size_t)3 * Cc * Cc;

    cudaFuncSetAttribute(gemm_mma<0>, cudaFuncAttributeMaxDynamicSharedMemorySize, GEMM_SMEM);
    cudaFuncSetAttribute(gemm_mma<1>, cudaFuncAttributeMaxDynamicSharedMemorySize, GEMM_SMEM);
    cudaFuncSetAttribute(gemm_mma<2>, cudaFuncAttributeMaxDynamicSharedMemorySize, GEMM_SMEM);
    cudaFuncSetAttribute(gemm_mma<4>, cudaFuncAttributeMaxDynamicSharedMemorySize, GEMM_SMEM);
    cudaFuncSetAttribute(gemm_mma<5>, cudaFuncAttributeMaxDynamicSharedMemorySize, GEMM_SMEM);

    cvt4_kernel<<<dim3(Cc * Cc / 1024, 4), 256>>>(wq, wk, wv, wo, w4);

    gn_stats_kernel<<<Bb * GROUPS, 256>>>(x, stats);
    gn_transpose_kernel<<<dim3(Nn / 64, Cc / 64, Bb), 256>>>(x, stats, gn_w, gn_b, h);

    const size_t sNC = (size_t)Nn * Cc;
    const size_t sCN = (size_t)Cc * Nn;
    const size_t sNN = (size_t)Nn * Nn;

    // q,k: D[n][o] = h[n,:] . wq[o,:] -> bf16 [N,C], bias over cols
    gemm_mma<1><<<dim3(Cc / TILE_N, Nn / TILE_M, Bb), 256, GEMM_SMEM>>>(
        h, sNC, Cc, bwq, 0, Cc, q, sNC, Cc, bq, nullptr, 0, Cc);
    gemm_mma<1><<<dim3(Cc / TILE_N, Nn / TILE_M, Bb), 256, GEMM_SMEM>>>(
        h, sNC, Cc, bwk, 0, Cc, k, sNC, Cc, bk, nullptr, 0, Cc);
    // v: D[o][n] = wv[o,:] . h[n,:] -> bf16 [C,N], bias over rows
    gemm_mma<2><<<dim3(Nn / TILE_N, Cc / TILE_M, Bb), 256, GEMM_SMEM>>>(
        bwv, 0, Cc, h, sNC, Cc, v, sCN, Nn, bv, nullptr, 0, Cc);
    // E: exp(q.k * scale) -> bf16 [N,N] + deterministic row partial sums
    gemm_mma<0><<<dim3(Nn / TILE_N, Nn / TILE_M, Bb), 256, GEMM_SMEM>>>(
        q, sNC, Cc, k, sNC, Cc, p, sNN, Nn, nullptr, part, 0, Cc);

    rowsum_kernel<<<(Bb * Nn) / 256, 256>>>(part, rsum);

    // attn: D[n][c] = (E[n,:] . v[c,:]) / rowsum[n] -> bf16 [N,C]
    gemm_mma<5><<<dim3(Cc / TILE_N, Nn / TILE_M, Bb), 256, GEMM_SMEM>>>(
        p, sNN, Nn, v, sCN, Nn, attn, sNC, Cc, nullptr, rsum, Nn, Nn);
    // out: D[o][n] = wo[o,:] . attn[n,:] + bo + x -> fp32 [C,N]
    gemm_mma<4><<<dim3(Nn / TILE_N, Cc / TILE_M, Bb), 256, GEMM_SMEM>>>(
        bwo, 0, Cc, attn, sNC, Cc, out, sCN, Nn, bo, x, sCN, Cc);
}

// round 14
// speedup vs baseline: 1.1601x; 1.0187x over previous
#include <cuda_runtime.h>
#include <cuda_bf16.h>
#include <math.h>
#include <stdint.h>

#define Bb 4
#define Cc 512
#define Nn 4096
#define GROUPS 32
#define CPG 16
#define EPS 1e-5f
#define SCALE 0.044194173824159216f  // 512^-0.5

// ---------------- scratch (device globals; no allocs allowed) ----------------
__device__ __nv_bfloat16 g_h[(size_t)Bb * Nn * Cc];     // [B][N][C]
__device__ __nv_bfloat16 g_q[(size_t)Bb * Nn * Cc];     // [B][N][C]
__device__ __nv_bfloat16 g_k[(size_t)Bb * Nn * Cc];     // [B][N][C]
__device__ __nv_bfloat16 g_v[(size_t)Bb * Cc * Nn];     // [B][C][N]
__device__ __nv_bfloat16 g_attn[(size_t)Bb * Nn * Cc];  // [B][N][C]
__device__ __nv_bfloat16 g_p[(size_t)Bb * Nn * Nn];     // [B][N][N] bf16 exp(logits)
__device__ float         g_part[(size_t)Bb * Nn * 32];  // per-(row, col-tile) exp partial sums
__device__ float         g_rsum[Bb * Nn];               // softmax denominators
__device__ float         g_stats[Bb * GROUPS * 2];      // mean, inv per (b,g)
__device__ __nv_bfloat16 g_w4[4 * Cc * Cc];             // wq|wk|wv|wo bf16

// ---------------- helpers ----------------
__device__ __forceinline__ uint32_t smem_u32(const void* p) {
    uint32_t a;
    asm("{ .reg .u64 t; cvta.to.shared.u64 t, %1; cvt.u32.u64 %0, t; }" : "=r"(a) : "l"(p));
    return a;
}
__device__ __forceinline__ uint32_t pack_bf2(float a, float b) {
    __nv_bfloat162 t = __float22bfloat162_rn(make_float2(a, b));
    return *reinterpret_cast<uint32_t*>(&t);
}
__device__ __forceinline__ void cp_async16(uint32_t saddr, const void* gptr) {
    asm volatile("cp.async.cg.shared.global [%0], [%1], 16;" :: "r"(saddr), "l"(gptr));
}
__device__ __forceinline__ void cp_commit() {
    asm volatile("cp.async.commit_group;");
}
template<int N>
__device__ __forceinline__ void cp_wait() {
    asm volatile("cp.async.wait_group %0;" :: "n"(N));
}
__device__ __forceinline__ void ldm_x4(uint32_t& r0, uint32_t& r1, uint32_t& r2, uint32_t& r3, uint32_t addr) {
    asm volatile("ldmatrix.sync.aligned.m8n8.x4.shared.b16 {%0,%1,%2,%3}, [%4];"
                 : "=r"(r0), "=r"(r1), "=r"(r2), "=r"(r3) : "r"(addr));
}
__device__ __forceinline__ void mma_bf16(float& c0, float& c1, float& c2, float& c3,
                                         uint32_t a0, uint32_t a1, uint32_t a2, uint32_t a3,
                                         uint32_t b0, uint32_t b1) {
    asm volatile(
        "mma.sync.aligned.m16n8k16.row.col.f32.bf16.bf16.f32 "
        "{%0,%1,%2,%3}, {%4,%5,%6,%7}, {%8,%9}, {%0,%1,%2,%3};"
        : "+f"(c0), "+f"(c1), "+f"(c2), "+f"(c3)
        : "r"(a0), "r"(a1), "r"(a2), "r"(a3), "r"(b0), "r"(b1));
}

// ---------------- GroupNorm stats ----------------
__global__ __launch_bounds__(256) void gn_stats_kernel(const float* __restrict__ x, float* __restrict__ stats) {
    const int bg = blockIdx.x;
    const size_t base = (size_t)bg * CPG * Nn;
    const float* xp = x + base;
    const int total = CPG * Nn;
    float s = 0.f, ss = 0.f;
    for (int i = threadIdx.x * 4; i < total; i += 1024) {
        float4 v = *(const float4*)(xp + i);
        s += v.x + v.y + v.z + v.w;
        ss += v.x * v.x + v.y * v.y + v.z * v.z + v.w * v.w;
    }
    __shared__ float rs[256], rss[256];
    rs[threadIdx.x] = s; rss[threadIdx.x] = ss;
    __syncthreads();
    for (int o = 128; o > 0; o >>= 1) {
        if (threadIdx.x < o) { rs[threadIdx.x] += rs[threadIdx.x + o]; rss[threadIdx.x] += rss[threadIdx.x + o]; }
        __syncthreads();
    }
    if (threadIdx.x == 0) {
        float mean = rs[0] / (float)total;
        float var = rss[0] / (float)total - mean * mean;
        stats[bg * 2] = mean;
        stats[bg * 2 + 1] = rsqrtf(var + EPS);
    }
}

// ---------------- normalize + transpose: x[B,C,N] -> h[B,N,C] bf16 ----------------
__global__ __launch_bounds__(256) void gn_transpose_kernel(
    const float* __restrict__ x, const float* __restrict__ stats,
    const float* __restrict__ w, const float* __restrict__ b,
    __nv_bfloat16* __restrict__ h)
{
    const int bz = blockIdx.z;
    const int c0 = blockIdx.y * 64;
    const int n0 = blockIdx.x * 64;
    __shared__ float ts[64][65];
    const size_t xoff = (size_t)bz * Cc * Nn;
    #pragma unroll
    for (int i = 0; i < 16; i++) {
        int idx = threadIdx.x + i * 256;
        int cl = idx >> 6, nl = idx & 63;
        int c = c0 + cl;
        float mean = stats[(bz * GROUPS + (c >> 4)) * 2];
        float inv  = stats[(bz * GROUPS + (c >> 4)) * 2 + 1];
        float val = x[xoff + (size_t)c * Nn + n0 + nl];
        ts[nl][cl] = (val - mean) * inv * __ldg(w + c) + __ldg(b + c);
    }
    __syncthreads();
    const size_t hoff = (size_t)bz * Nn * Cc;
    #pragma unroll
    for (int i = 0; i < 16; i++) {
        int idx = threadIdx.x + i * 256;
        int nl = idx >> 6, cl = idx & 63;
        h[hoff + (size_t)(n0 + nl) * Cc + c0 + cl] = __float2bfloat16_rn(ts[nl][cl]);
    }
}

// ---------------- fp32 -> bf16 weight convert ----------------
__global__ __launch_bounds__(256) void cvt4_kernel(
    const float* __restrict__ w0, const float* __restrict__ w1,
    const float* __restrict__ w2, const float* __restrict__ w3,
    __nv_bfloat16* __restrict__ dst)
{
    const int which = blockIdx.y;
    const float* src = which == 0 ? w0 : which == 1 ? w1 : which == 2 ? w2 : w3;
    __nv_bfloat16* d = dst + (size_t)which * Cc * Cc;
    int i = (blockIdx.x * 256 + threadIdx.x) * 4;
    if (i < Cc * Cc) {
        float4 v = *(const float4*)(src + i);
        uint2 o;
        o.x = pack_bf2(v.x, v.y);
        o.y = pack_bf2(v.z, v.w);
        *(uint2*)((char*)d + (size_t)i * 2) = o;
    }
}

// ---------------- rowsum reduce: 32 partials per row -> denominator ----------------
__global__ __launch_bounds__(256) void rowsum_kernel(const float* __restrict__ part, float* __restrict__ rsum) {
    int i = blockIdx.x * 256 + threadIdx.x;
    if (i < Bb * Nn) {
        const float4* p = (const float4*)(part + (size_t)i * 32);
        float s = 0.f;
        #pragma unroll
        for (int j = 0; j < 8; j++) {
            float4 f = p[j];
            s += f.x + f.y + f.z + f.w;
        }
        rsum[i] = s;
    }
}

// ---------------- mma.sync bf16 GEMM:  D[M,N] = A[M,K] * B[N,K]^T ----------------
// CTA tile 128x128, BK=64 (128B swizzled rows), 3-stage cp.async, 8 warps (2x4) each 64x32.
// Mainloop: single barrier per iter; next-stage cp.async issued BEFORE compute (overlap).
// EPI: 0 = exp(acc*SCALE) -> bf16 E + deterministic row partial sums
//      1 = bf16 + bias[col] | 2 = bf16 + bias[row]
//      4 = fp32 + bias[row] + residual | 5 = bf16 * (1/rowsum[row])
#define BKq 64
#define STAGES 3
#define TILE_M 128
#define TILE_N 128
#define STG_ELEMS (TILE_M * BKq)
#define GEMM_SMEM (STAGES * 2 * STG_ELEMS * 2)   // 98304 bytes

// element offset (bf16 units) of (row r, elem c) in a swizzled [128][64] tile
__device__ __forceinline__ uint32_t sw_idx(uint32_t r, uint32_t c) {
    uint32_t chunk = c >> 3, within = c & 7;
    return (r << 6) + (((chunk ^ (r & 7)) << 3) | within);
}

template<int EPI>
__global__ __launch_bounds__(256, 2) void gemm_mma(
    const __nv_bfloat16* __restrict__ A, size_t strA, int ldA,
    const __nv_bfloat16* __restrict__ B, size_t strB, int ldB,
    void* __restrict__ Out, size_t sOut, int ldOut,
    const float* __restrict__ bias,
    const float* __restrict__ Aux, size_t sAux,   // EPI0: partials | EPI4: residual | EPI5: rowsum
    int K)
{
    extern __shared__ __nv_bfloat16 dyn[];

    const int tid = threadIdx.x;
    const int lane = tid & 31, wid = tid >> 5;
    const int wm = (wid & 1) * 64;      // warp M offset
    const int wn = (wid >> 1) * 32;     // warp N offset
    const int bz = blockIdx.z;

    const __nv_bfloat16* Ab = A + bz * strA + (size_t)(blockIdx.y * TILE_M) * ldA;
    const __nv_bfloat16* Bp = B + bz * strB + (size_t)(blockIdx.x * TILE_N) * ldB;

    auto load_chunk = [&](int chunk, int buf) {
        const int k0 = chunk * BKq;
        __nv_bfloat16* baseA = dyn + (size_t)buf * STG_ELEMS;
        __nv_bfloat16* baseB = dyn + (size_t)(STAGES + buf) * STG_ELEMS;
        #pragma unroll
        for (int j = 0; j < 4; j++) {
            int idx = tid + j * 256;
            int r = idx >> 3, ck = idx & 7;
            cp_async16(smem_u32(baseA + sw_idx(r, ck * 8)), Ab + (size_t)r * ldA + k0 + ck * 8);
        }
        #pragma unroll
        for (int j = 0; j < 4; j++) {
            int idx = tid + j * 256;
            int r = idx >> 3, ck = idx & 7;
            cp_async16(smem_u32(baseB + sw_idx(r, ck * 8)), Bp + (size_t)r * ldB + k0 + ck * 8);
        }
        cp_commit();
    };

    float acc[4][4][4];
    #pragma unroll
    for (int i = 0; i < 4; i++)
        #pragma unroll
        for (int j = 0; j < 4; j++)
            #pragma unroll
            for (int t = 0; t < 4; t++) acc[i][j][t] = 0.f;

    const int nc = K / BKq;
    #pragma unroll
    for (int s = 0; s < STAGES - 1; s++) load_chunk(s, s);

    for (int i = 0; i < nc; i++) {
        cp_wait<STAGES - 2>();
        __syncthreads();
        // issue next stage's loads FIRST so GMEM latency overlaps the compute below.
        // Safe: buf (i+2)%3 was last read in compute(i-1); all threads passed this barrier.
        if (i + STAGES - 1 < nc) load_chunk(i + STAGES - 1, (i + STAGES - 1) % STAGES);
        else cp_commit();   // keep one commit per iter so wait_group 1 drains stage i

        const int buf = i % STAGES;
        const uint32_t sAb = smem_u32(dyn + (size_t)buf * STG_ELEMS);
        const uint32_t sBb = smem_u32(dyn + (size_t)(STAGES + buf) * STG_ELEMS);

        #pragma unroll
        for (int ks = 0; ks < 4; ks++) {
            const uint32_t cb = ks * 2 + (lane >> 4);   // 16B chunk index (0..7)
            uint32_t a[4][4];
            #pragma unroll
            for (int mt = 0; mt < 4; mt++) {
                uint32_t r = wm + mt * 16 + (lane & 15);
                ldm_x4(a[mt][0], a[mt][1], a[mt][2], a[mt][3], sAb + (sw_idx(r, cb << 3) << 1));
            }
            uint32_t br[2][4];
            #pragma unroll
            for (int ntp = 0; ntp < 2; ntp++) {
                uint32_t r = wn + ntp * 16 + (lane & 15);
                ldm_x4(br[ntp][0], br[ntp][1], br[ntp][2], br[ntp][3], sBb + (sw_idx(r, cb << 3) << 1));
            }
            #pragma unroll
            for (int mt = 0; mt < 4; mt++)
                #pragma unroll
                for (int nt = 0; nt < 4; nt++) {
                    int ntp = nt >> 1, sel = nt & 1;
                    mma_bf16(acc[mt][nt][0], acc[mt][nt][1], acc[mt][nt][2], acc[mt][nt][3],
                             a[mt][0], a[mt][1], a[mt][2], a[mt][3],
                             br[ntp][sel], br[ntp][sel + 2]);
                }
        }
    }

    // -------- epilogue --------
    const int rbase = blockIdx.y * TILE_M + wm + (lane >> 2);
    const int cbase = blockIdx.x * TILE_N + wn + ((lane & 3) << 1);

    float rsum8[8];
    #pragma unroll
    for (int t = 0; t < 8; t++) rsum8[t] = 0.f;

    #pragma unroll
    for (int mt = 0; mt < 4; mt++) {
        #pragma unroll
        for (int half = 0; half < 2; half++) {
            const int row = rbase + mt * 16 + half * 8;
            float brow = (EPI == 2 || EPI == 4) ? __ldg(bias + row) : 0.f;
            float inv = 1.f;
            if (EPI == 5) inv = 1.0f / __ldg(Aux + (size_t)bz * sAux + row);
            #pragma unroll
            for (int nt = 0; nt < 4; nt++) {
                const int col = cbase + nt * 8;
                float v0 = acc[mt][nt][half * 2 + 0];
                float v1 = acc[mt][nt][half * 2 + 1];
                if (EPI == 0) {
                    float e0 = __expf(v0 * SCALE);
                    float e1 = __expf(v1 * SCALE);
                    rsum8[mt * 2 + half] += e0 + e1;
                    __nv_bfloat16* op = (__nv_bfloat16*)Out + bz * sOut + (size_t)row * ldOut + col;
                    *(uint32_t*)op = pack_bf2(e0, e1);
                } else if (EPI == 4) {
                    const float* rp = Aux + bz * sAux + (size_t)row * ldOut + col;
                    float2 rv = *(const float2*)rp;
                    float* op = (float*)Out + bz * sOut + (size_t)row * ldOut + col;
                    *(float2*)op = make_float2(v0 + brow + rv.x, v1 + brow + rv.y);
                } else if (EPI == 5) {
                    __nv_bfloat16* op = (__nv_bfloat16*)Out + bz * sOut + (size_t)row * ldOut + col;
                    *(uint32_t*)op = pack_bf2(v0 * inv, v1 * inv);
                } else {
                    float b0 = 0.f, b1 = 0.f;
                    if (EPI == 1) { b0 = __ldg(bias + col); b1 = __ldg(bias + col + 1); }
                    else if (EPI == 2) { b0 = brow; b1 = brow; }
                    __nv_bfloat16* op = (__nv_bfloat16*)Out + bz * sOut + (size_t)row * ldOut + col;
                    *(uint32_t*)op = pack_bf2(v0 + b0, v1 + b1);
                }
            }
        }
    }

    if (EPI == 0) {
        // deterministic per-row partial sums: quad shuffle -> smem cross-warp -> global
        float (*srs)[4] = (float (*)[4])dyn;
        __syncthreads();   // mainloop smem reads complete before reuse
        #pragma unroll
        for (int t = 0; t < 8; t++) {
            float r = rsum8[t];
            r += __shfl_xor_sync(0xFFFFFFFFu, r, 1);
            r += __shfl_xor_sync(0xFFFFFFFFu, r, 2);
            if ((lane & 3) == 0) {
                int mt = t >> 1, half = t & 1;
                int lrow = wm + mt * 16 + half * 8 + (lane >> 2);
                srs[lrow][wid >> 1] = r;
            }
        }
        __syncthreads();
        if (tid < 128) {
            float s = srs[tid][0] + srs[tid][1] + srs[tid][2] + srs[tid][3];
            float* part = (float*)Aux;
            part[((size_t)bz * Nn + blockIdx.y * TILE_M + tid) * 32 + blockIdx.x] = s;
        }
    }
}

// ---------------- launch ----------------
extern "C" void kernel_launch(void* const* d_in, const int* in_sizes, int n_in,
                              void* d_out, int out_size)
{
    const float* x    = (const float*)d_in[0];
    const float* gn_w = (const float*)d_in[1];
    const float* gn_b = (const float*)d_in[2];
    const float* wq   = (const float*)d_in[3];
    const float* bq   = (const float*)d_in[4];
    const float* wk   = (const float*)d_in[5];
    const float* bk   = (const float*)d_in[6];
    const float* wv   = (const float*)d_in[7];
    const float* bv   = (const float*)d_in[8];
    const float* wo   = (const float*)d_in[9];
    const float* bo   = (const float*)d_in[10];
    float* out = (float*)d_out;

    __nv_bfloat16 *h, *q, *k, *v, *attn, *p, *w4;
    float *stats, *part, *rsum;
    cudaGetSymbolAddress((void**)&h, g_h);
    cudaGetSymbolAddress((void**)&q, g_q);
    cudaGetSymbolAddress((void**)&k, g_k);
    cudaGetSymbolAddress((void**)&v, g_v);
    cudaGetSymbolAddress((void**)&attn, g_attn);
    cudaGetSymbolAddress((void**)&p, g_p);
    cudaGetSymbolAddress((void**)&stats, g_stats);
    cudaGetSymbolAddress((void**)&part, g_part);
    cudaGetSymbolAddress((void**)&rsum, g_rsum);
    cudaGetSymbolAddress((void**)&w4, g_w4);
    __nv_bfloat16* bwq = w4;
    __nv_bfloat16* bwk = w4 + (size_t)Cc * Cc;
    __nv_bfloat16* bwv = w4 + (size_t)2 * Cc * Cc;
    __nv_bfloat16* bwo = w4 + (size_t)3 * Cc * Cc;

    cudaFuncSetAttribute(gemm_mma<0>, cudaFuncAttributeMaxDynamicSharedMemorySize, GEMM_SMEM);
    cudaFuncSetAttribute(gemm_mma<1>, cudaFuncAttributeMaxDynamicSharedMemorySize, GEMM_SMEM);
    cudaFuncSetAttribute(gemm_mma<2>, cudaFuncAttributeMaxDynamicSharedMemorySize, GEMM_SMEM);
    cudaFuncSetAttribute(gemm_mma<4>, cudaFuncAttributeMaxDynamicSharedMemorySize, GEMM_SMEM);
    cudaFuncSetAttribute(gemm_mma<5>, cudaFuncAttributeMaxDynamicSharedMemorySize, GEMM_SMEM);

    cvt4_kernel<<<dim3(Cc * Cc / 1024, 4), 256>>>(wq, wk, wv, wo, w4);

    gn_stats_kernel<<<Bb * GROUPS, 256>>>(x, stats);
    gn_transpose_kernel<<<dim3(Nn / 64, Cc / 64, Bb), 256>>>(x, stats, gn_w, gn_b, h);

    const size_t sNC = (size_t)Nn * Cc;
    const size_t sCN = (size_t)Cc * Nn;
    const size_t sNN = (size_t)Nn * Nn;

    // q,k: D[n][o] = h[n,:] . wq[o,:] -> bf16 [N,C], bias over cols
    gemm_mma<1><<<dim3(Cc / TILE_N, Nn / TILE_M, Bb), 256, GEMM_SMEM>>>(
        h, sNC, Cc, bwq, 0, Cc, q, sNC, Cc, bq, nullptr, 0, Cc);
    gemm_mma<1><<<dim3(Cc / TILE_N, Nn / TILE_M, Bb), 256, GEMM_SMEM>>>(
        h, sNC, Cc, bwk, 0, Cc, k, sNC, Cc, bk, nullptr, 0, Cc);
    // v: D[o][n] = wv[o,:] . h[n,:] -> bf16 [C,N], bias over rows
    gemm_mma<2><<<dim3(Nn / TILE_N, Cc / TILE_M, Bb), 256, GEMM_SMEM>>>(
        bwv, 0, Cc, h, sNC, Cc, v, sCN, Nn, bv, nullptr, 0, Cc);
    // E: exp(q.k * scale) -> bf16 [N,N] + deterministic row partial sums
    gemm_mma<0><<<dim3(Nn / TILE_N, Nn / TILE_M, Bb), 256, GEMM_SMEM>>>(
        q, sNC, Cc, k, sNC, Cc, p, sNN, Nn, nullptr, part, 0, Cc);

    rowsum_kernel<<<(Bb * Nn) / 256, 256>>>(part, rsum);

    // attn: D[n][c] = (E[n,:] . v[c,:]) / rowsum[n] -> bf16 [N,C]
    gemm_mma<5><<<dim3(Cc / TILE_N, Nn / TILE_M, Bb), 256, GEMM_SMEM>>>(
        p, sNN, Nn, v, sCN, Nn, attn, sNC, Cc, nullptr, rsum, Nn, Nn);
    // out: D[o][n] = wo[o,:] . attn[n,:] + bo + x -> fp32 [C,N]
    gemm_mma<4><<<dim3(Nn / TILE_N, Cc / TILE_M, Bb), 256, GEMM_SMEM>>>(
        bwo, 0, Cc, attn, sNC, Cc, out, sCN, Nn, bo, x, sCN, Cc);
}

// round 15
// speedup vs baseline: 1.1785x; 1.0159x over previous
#include <cuda_runtime.h>
#include <cuda_bf16.h>
#include <math.h>
#include <stdint.h>

#define Bb 4
#define Cc 512
#define Nn 4096
#define GROUPS 32
#define CPG 16
#define EPS 1e-5f
#define SCALE 0.044194173824159216f  // 512^-0.5

// ---------------- scratch (device globals; no allocs allowed) ----------------
__device__ __nv_bfloat16 g_h[(size_t)Bb * Nn * Cc];      // [B][N][C]
__device__ __nv_bfloat16 g_qk[(size_t)Bb * Nn * 2 * Cc]; // [B][N][2C]: q | k
__device__ __nv_bfloat16 g_v[(size_t)Bb * Cc * Nn];      // [B][C][N]
__device__ __nv_bfloat16 g_attn[(size_t)Bb * Nn * Cc];   // [B][N][C]
__device__ __nv_bfloat16 g_p[(size_t)Bb * Nn * Nn];      // [B][N][N] bf16 exp(logits)
__device__ float         g_part[(size_t)Bb * Nn * 32];   // per-(row, col-tile) exp partial sums
__device__ float         g_rsum[Bb * Nn];                // softmax denominators
__device__ float         g_stats[Bb * GROUPS * 2];       // mean, inv per (b,g)
__device__ float         g_bqk[2 * Cc];                  // packed bq | bk
__device__ __nv_bfloat16 g_w4[4 * Cc * Cc];              // wq|wk|wv|wo bf16

// ---------------- helpers ----------------
__device__ __forceinline__ uint32_t smem_u32(const void* p) {
    uint32_t a;
    asm("{ .reg .u64 t; cvta.to.shared.u64 t, %1; cvt.u32.u64 %0, t; }" : "=r"(a) : "l"(p));
    return a;
}
__device__ __forceinline__ uint32_t pack_bf2(float a, float b) {
    __nv_bfloat162 t = __float22bfloat162_rn(make_float2(a, b));
    return *reinterpret_cast<uint32_t*>(&t);
}
__device__ __forceinline__ void cp_async16(uint32_t saddr, const void* gptr) {
    asm volatile("cp.async.cg.shared.global [%0], [%1], 16;" :: "r"(saddr), "l"(gptr));
}
__device__ __forceinline__ void cp_commit() {
    asm volatile("cp.async.commit_group;");
}
template<int N>
__device__ __forceinline__ void cp_wait() {
    asm volatile("cp.async.wait_group %0;" :: "n"(N));
}
__device__ __forceinline__ void ldm_x4(uint32_t& r0, uint32_t& r1, uint32_t& r2, uint32_t& r3, uint32_t addr) {
    asm volatile("ldmatrix.sync.aligned.m8n8.x4.shared.b16 {%0,%1,%2,%3}, [%4];"
                 : "=r"(r0), "=r"(r1), "=r"(r2), "=r"(r3) : "r"(addr));
}
__device__ __forceinline__ void mma_bf16(float& c0, float& c1, float& c2, float& c3,
                                         uint32_t a0, uint32_t a1, uint32_t a2, uint32_t a3,
                                         uint32_t b0, uint32_t b1) {
    asm volatile(
        "mma.sync.aligned.m16n8k16.row.col.f32.bf16.bf16.f32 "
        "{%0,%1,%2,%3}, {%4,%5,%6,%7}, {%8,%9}, {%0,%1,%2,%3};"
        : "+f"(c0), "+f"(c1), "+f"(c2), "+f"(c3)
        : "r"(a0), "r"(a1), "r"(a2), "r"(a3), "r"(b0), "r"(b1));
}

// ---------------- GroupNorm stats ----------------
__global__ __launch_bounds__(256) void gn_stats_kernel(const float* __restrict__ x, float* __restrict__ stats) {
    const int bg = blockIdx.x;
    const size_t base = (size_t)bg * CPG * Nn;
    const float* xp = x + base;
    const int total = CPG * Nn;
    float s = 0.f, ss = 0.f;
    for (int i = threadIdx.x * 4; i < total; i += 1024) {
        float4 v = *(const float4*)(xp + i);
        s += v.x + v.y + v.z + v.w;
        ss += v.x * v.x + v.y * v.y + v.z * v.z + v.w * v.w;
    }
    __shared__ float rs[256], rss[256];
    rs[threadIdx.x] = s; rss[threadIdx.x] = ss;
    __syncthreads();
    for (int o = 128; o > 0; o >>= 1) {
        if (threadIdx.x < o) { rs[threadIdx.x] += rs[threadIdx.x + o]; rss[threadIdx.x] += rss[threadIdx.x + o]; }
        __syncthreads();
    }
    if (threadIdx.x == 0) {
        float mean = rs[0] / (float)total;
        float var = rss[0] / (float)total - mean * mean;
        stats[bg * 2] = mean;
        stats[bg * 2 + 1] = rsqrtf(var + EPS);
    }
}

// ---------------- normalize + transpose: x[B,C,N] -> h[B,N,C] bf16 ----------------
__global__ __launch_bounds__(256) void gn_transpose_kernel(
    const float* __restrict__ x, const float* __restrict__ stats,
    const float* __restrict__ w, const float* __restrict__ b,
    __nv_bfloat16* __restrict__ h)
{
    const int bz = blockIdx.z;
    const int c0 = blockIdx.y * 64;
    const int n0 = blockIdx.x * 64;
    __shared__ float ts[64][65];
    const size_t xoff = (size_t)bz * Cc * Nn;
    #pragma unroll
    for (int i = 0; i < 16; i++) {
        int idx = threadIdx.x + i * 256;
        int cl = idx >> 6, nl = idx & 63;
        int c = c0 + cl;
        float mean = stats[(bz * GROUPS + (c >> 4)) * 2];
        float inv  = stats[(bz * GROUPS + (c >> 4)) * 2 + 1];
        float val = x[xoff + (size_t)c * Nn + n0 + nl];
        ts[nl][cl] = (val - mean) * inv * __ldg(w + c) + __ldg(b + c);
    }
    __syncthreads();
    const size_t hoff = (size_t)bz * Nn * Cc;
    #pragma unroll
    for (int i = 0; i < 16; i++) {
        int idx = threadIdx.x + i * 256;
        int nl = idx >> 6, cl = idx & 63;
        h[hoff + (size_t)(n0 + nl) * Cc + c0 + cl] = __float2bfloat16_rn(ts[nl][cl]);
    }
}

// ---------------- fp32 -> bf16 weight convert + bias pack ----------------
__global__ __launch_bounds__(256) void cvt4_kernel(
    const float* __restrict__ w0, const float* __restrict__ w1,
    const float* __restrict__ w2, const float* __restrict__ w3,
    __nv_bfloat16* __restrict__ dst,
    const float* __restrict__ bq, const float* __restrict__ bk,
    float* __restrict__ bqk)
{
    const int which = blockIdx.y;
    const float* src = which == 0 ? w0 : which == 1 ? w1 : which == 2 ? w2 : w3;
    __nv_bfloat16* d = dst + (size_t)which * Cc * Cc;
    int i = (blockIdx.x * 256 + threadIdx.x) * 4;
    if (i < Cc * Cc) {
        float4 v = *(const float4*)(src + i);
        uint2 o;
        o.x = pack_bf2(v.x, v.y);
        o.y = pack_bf2(v.z, v.w);
        *(uint2*)((char*)d + (size_t)i * 2) = o;
    }
    // bias pack: first 2 y-slices, first 512 linear threads each
    int t = blockIdx.x * 256 + threadIdx.x;
    if (which == 0 && t < Cc) bqk[t] = bq[t];
    if (which == 1 && t < Cc) bqk[Cc + t] = bk[t];
}

// ---------------- rowsum reduce: 32 partials per row -> denominator ----------------
__global__ __launch_bounds__(256) void rowsum_kernel(const float* __restrict__ part, float* __restrict__ rsum) {
    int i = blockIdx.x * 256 + threadIdx.x;
    if (i < Bb * Nn) {
        const float4* p = (const float4*)(part + (size_t)i * 32);
        float s = 0.f;
        #pragma unroll
        for (int j = 0; j < 8; j++) {
            float4 f = p[j];
            s += f.x + f.y + f.z + f.w;
        }
        rsum[i] = s;
    }
}

// ---------------- mma.sync bf16 GEMM:  D[M,N] = A[M,K] * B[N,K]^T ----------------
// CTA tile 128x128, BK=64 (128B swizzled rows), 3-stage cp.async, 8 warps (2x4) each 64x32.
// Mainloop: single barrier per iter; next-stage cp.async issued BEFORE compute (overlap).
// EPI: 0 = exp(acc*SCALE) -> bf16 E + deterministic row partial sums
//      1 = bf16 + bias[col] | 2 = bf16 + bias[row]
//      4 = fp32 + bias[row] + residual | 5 = bf16 * (1/rowsum[row])
#define BKq 64
#define STAGES 3
#define TILE_M 128
#define TILE_N 128
#define STG_ELEMS (TILE_M * BKq)
#define GEMM_SMEM (STAGES * 2 * STG_ELEMS * 2)   // 98304 bytes

// element offset (bf16 units) of (row r, elem c) in a swizzled [128][64] tile
__device__ __forceinline__ uint32_t sw_idx(uint32_t r, uint32_t c) {
    uint32_t chunk = c >> 3, within = c & 7;
    return (r << 6) + (((chunk ^ (r & 7)) << 3) | within);
}

template<int EPI>
__global__ __launch_bounds__(256, 2) void gemm_mma(
    const __nv_bfloat16* __restrict__ A, size_t strA, int ldA,
    const __nv_bfloat16* __restrict__ B, size_t strB, int ldB,
    void* __restrict__ Out, size_t sOut, int ldOut,
    const float* __restrict__ bias,
    const float* __restrict__ Aux, size_t sAux,   // EPI0: partials | EPI4: residual | EPI5: rowsum
    int K)
{
    extern __shared__ __nv_bfloat16 dyn[];

    const int tid = threadIdx.x;
    const int lane = tid & 31, wid = tid >> 5;
    const int wm = (wid & 1) * 64;      // warp M offset
    const int wn = (wid >> 1) * 32;     // warp N offset
    const int bz = blockIdx.z;

    const __nv_bfloat16* Ab = A + bz * strA + (size_t)(blockIdx.y * TILE_M) * ldA;
    const __nv_bfloat16* Bp = B + bz * strB + (size_t)(blockIdx.x * TILE_N) * ldB;

    auto load_chunk = [&](int chunk, int buf) {
        const int k0 = chunk * BKq;
        __nv_bfloat16* baseA = dyn + (size_t)buf * STG_ELEMS;
        __nv_bfloat16* baseB = dyn + (size_t)(STAGES + buf) * STG_ELEMS;
        #pragma unroll
        for (int j = 0; j < 4; j++) {
            int idx = tid + j * 256;
            int r = idx >> 3, ck = idx & 7;
            cp_async16(smem_u32(baseA + sw_idx(r, ck * 8)), Ab + (size_t)r * ldA + k0 + ck * 8);
        }
        #pragma unroll
        for (int j = 0; j < 4; j++) {
            int idx = tid + j * 256;
            int r = idx >> 3, ck = idx & 7;
            cp_async16(smem_u32(baseB + sw_idx(r, ck * 8)), Bp + (size_t)r * ldB + k0 + ck * 8);
        }
        cp_commit();
    };

    float acc[4][4][4];
    #pragma unroll
    for (int i = 0; i < 4; i++)
        #pragma unroll
        for (int j = 0; j < 4; j++)
            #pragma unroll
            for (int t = 0; t < 4; t++) acc[i][j][t] = 0.f;

    const int nc = K / BKq;
    #pragma unroll
    for (int s = 0; s < STAGES - 1; s++) load_chunk(s, s);

    for (int i = 0; i < nc; i++) {
        cp_wait<STAGES - 2>();
        __syncthreads();
        // issue next stage's loads FIRST so GMEM latency overlaps the compute below.
        // Safe: buf (i+2)%3 was last read in compute(i-1); all threads passed this barrier.
        if (i + STAGES - 1 < nc) load_chunk(i + STAGES - 1, (i + STAGES - 1) % STAGES);
        else cp_commit();   // keep one commit per iter so wait_group 1 drains stage i

        const int buf = i % STAGES;
        const uint32_t sAb = smem_u32(dyn + (size_t)buf * STG_ELEMS);
        const uint32_t sBb = smem_u32(dyn + (size_t)(STAGES + buf) * STG_ELEMS);

        #pragma unroll
        for (int ks = 0; ks < 4; ks++) {
            const uint32_t cb = ks * 2 + (lane >> 4);   // 16B chunk index (0..7)
            uint32_t a[4][4];
            #pragma unroll
            for (int mt = 0; mt < 4; mt++) {
                uint32_t r = wm + mt * 16 + (lane & 15);
                ldm_x4(a[mt][0], a[mt][1], a[mt][2], a[mt][3], sAb + (sw_idx(r, cb << 3) << 1));
            }
            uint32_t br[2][4];
            #pragma unroll
            for (int ntp = 0; ntp < 2; ntp++) {
                uint32_t r = wn + ntp * 16 + (lane & 15);
                ldm_x4(br[ntp][0], br[ntp][1], br[ntp][2], br[ntp][3], sBb + (sw_idx(r, cb << 3) << 1));
            }
            #pragma unroll
            for (int mt = 0; mt < 4; mt++)
                #pragma unroll
                for (int nt = 0; nt < 4; nt++) {
                    int ntp = nt >> 1, sel = nt & 1;
                    mma_bf16(acc[mt][nt][0], acc[mt][nt][1], acc[mt][nt][2], acc[mt][nt][3],
                             a[mt][0], a[mt][1], a[mt][2], a[mt][3],
                             br[ntp][sel], br[ntp][sel + 2]);
                }
        }
    }

    // -------- epilogue --------
    const int rbase = blockIdx.y * TILE_M + wm + (lane >> 2);
    const int cbase = blockIdx.x * TILE_N + wn + ((lane & 3) << 1);

    float rsum8[8];
    #pragma unroll
    for (int t = 0; t < 8; t++) rsum8[t] = 0.f;

    #pragma unroll
    for (int mt = 0; mt < 4; mt++) {
        #pragma unroll
        for (int half = 0; half < 2; half++) {
            const int row = rbase + mt * 16 + half * 8;
            float brow = (EPI == 2 || EPI == 4) ? __ldg(bias + row) : 0.f;
            float inv = 1.f;
            if (EPI == 5) inv = 1.0f / __ldg(Aux + (size_t)bz * sAux + row);
            #pragma unroll
            for (int nt = 0; nt < 4; nt++) {
                const int col = cbase + nt * 8;
                float v0 = acc[mt][nt][half * 2 + 0];
                float v1 = acc[mt][nt][half * 2 + 1];
                if (EPI == 0) {
                    float e0 = __expf(v0 * SCALE);
                    float e1 = __expf(v1 * SCALE);
                    rsum8[mt * 2 + half] += e0 + e1;
                    __nv_bfloat16* op = (__nv_bfloat16*)Out + bz * sOut + (size_t)row * ldOut + col;
                    *(uint32_t*)op = pack_bf2(e0, e1);
                } else if (EPI == 4) {
                    const float* rp = Aux + bz * sAux + (size_t)row * ldOut + col;
                    float2 rv = *(const float2*)rp;
                    float* op = (float*)Out + bz * sOut + (size_t)row * ldOut + col;
                    *(float2*)op = make_float2(v0 + brow + rv.x, v1 + brow + rv.y);
                } else if (EPI == 5) {
                    __nv_bfloat16* op = (__nv_bfloat16*)Out + bz * sOut + (size_t)row * ldOut + col;
                    *(uint32_t*)op = pack_bf2(v0 * inv, v1 * inv);
                } else {
                    float b0 = 0.f, b1 = 0.f;
                    if (EPI == 1) { b0 = __ldg(bias + col); b1 = __ldg(bias + col + 1); }
                    else if (EPI == 2) { b0 = brow; b1 = brow; }
                    __nv_bfloat16* op = (__nv_bfloat16*)Out + bz * sOut + (size_t)row * ldOut + col;
                    *(uint32_t*)op = pack_bf2(v0 + b0, v1 + b1);
                }
            }
        }
    }

    if (EPI == 0) {
        // deterministic per-row partial sums: quad shuffle -> smem cross-warp -> global
        float (*srs)[4] = (float (*)[4])dyn;
        __syncthreads();   // mainloop smem reads complete before reuse
        #pragma unroll
        for (int t = 0; t < 8; t++) {
            float r = rsum8[t];
            r += __shfl_xor_sync(0xFFFFFFFFu, r, 1);
            r += __shfl_xor_sync(0xFFFFFFFFu, r, 2);
            if ((lane & 3) == 0) {
                int mt = t >> 1, half = t & 1;
                int lrow = wm + mt * 16 + half * 8 + (lane >> 2);
                srs[lrow][wid >> 1] = r;
            }
        }
        __syncthreads();
        if (tid < 128) {
            float s = srs[tid][0] + srs[tid][1] + srs[tid][2] + srs[tid][3];
            float* part = (float*)Aux;
            part[((size_t)bz * Nn + blockIdx.y * TILE_M + tid) * 32 + blockIdx.x] = s;
        }
    }
}

// ---------------- launch ----------------
extern "C" void kernel_launch(void* const* d_in, const int* in_sizes, int n_in,
                              void* d_out, int out_size)
{
    const float* x    = (const float*)d_in[0];
    const float* gn_w = (const float*)d_in[1];
    const float* gn_b = (const float*)d_in[2];
    const float* wq   = (const float*)d_in[3];
    const float* bq   = (const float*)d_in[4];
    const float* wk   = (const float*)d_in[5];
    const float* bk   = (const float*)d_in[6];
    const float* wv   = (const float*)d_in[7];
    const float* bv   = (const float*)d_in[8];
    const float* wo   = (const float*)d_in[9];
    const float* bo   = (const float*)d_in[10];
    float* out = (float*)d_out;

    __nv_bfloat16 *h, *qk, *v, *attn, *p, *w4;
    float *stats, *part, *rsum, *bqk;
    cudaGetSymbolAddress((void**)&h, g_h);
    cudaGetSymbolAddress((void**)&qk, g_qk);
    cudaGetSymbolAddress((void**)&v, g_v);
    cudaGetSymbolAddress((void**)&attn, g_attn);
    cudaGetSymbolAddress((void**)&p, g_p);
    cudaGetSymbolAddress((void**)&stats, g_stats);
    cudaGetSymbolAddress((void**)&part, g_part);
    cudaGetSymbolAddress((void**)&rsum, g_rsum);
    cudaGetSymbolAddress((void**)&bqk, g_bqk);
    cudaGetSymbolAddress((void**)&w4, g_w4);
    __nv_bfloat16* bwqk = w4;                              // [2C, C] = wq rows then wk rows
    __nv_bfloat16* bwv  = w4 + (size_t)2 * Cc * Cc;
    __nv_bfloat16* bwo  = w4 + (size_t)3 * Cc * Cc;

    cudaFuncSetAttribute(gemm_mma<0>, cudaFuncAttributeMaxDynamicSharedMemorySize, GEMM_SMEM);
    cudaFuncSetAttribute(gemm_mma<1>, cudaFuncAttributeMaxDynamicSharedMemorySize, GEMM_SMEM);
    cudaFuncSetAttribute(gemm_mma<2>, cudaFuncAttributeMaxDynamicSharedMemorySize, GEMM_SMEM);
    cudaFuncSetAttribute(gemm_mma<4>, cudaFuncAttributeMaxDynamicSharedMemorySize, GEMM_SMEM);
    cudaFuncSetAttribute(gemm_mma<5>, cudaFuncAttributeMaxDynamicSharedMemorySize, GEMM_SMEM);

    cvt4_kernel<<<dim3(Cc * Cc / 1024, 4), 256>>>(wq, wk, wv, wo, w4, bq, bk, bqk);

    gn_stats_kernel<<<Bb * GROUPS, 256>>>(x, stats);
    gn_transpose_kernel<<<dim3(Nn / 64, Cc / 64, Bb), 256>>>(x, stats, gn_w, gn_b, h);

    const size_t sNC  = (size_t)Nn * Cc;
    const size_t sN2C = (size_t)Nn * 2 * Cc;
    const size_t sCN  = (size_t)Cc * Nn;
    const size_t sNN  = (size_t)Nn * Nn;

    // merged q,k: D[n][o] = h[n,:] . wqk[o,:]  (o in [0,1024)) -> bf16 [N, 2C], bias over cols
    gemm_mma<1><<<dim3(2 * Cc / TILE_N, Nn / TILE_M, Bb), 256, GEMM_SMEM>>>(
        h, sNC, Cc, bwqk, 0, Cc, qk, sN2C, 2 * Cc, bqk, nullptr, 0, Cc);
    // v: D[o][n] = wv[o,:] . h[n,:] -> bf16 [C,N], bias over rows
    gemm_mma<2><<<dim3(Nn / TILE_N, Cc / TILE_M, Bb), 256, GEMM_SMEM>>>(
        bwv, 0, Cc, h, sNC, Cc, v, sCN, Nn, bv, nullptr, 0, Cc);
    // E: exp(q.k * scale) -> bf16 [N,N] + deterministic row partial sums
    gemm_mma<0><<<dim3(Nn / TILE_N, Nn / TILE_M, Bb), 256, GEMM_SMEM>>>(
        qk, sN2C, 2 * Cc, qk + Cc, sN2C, 2 * Cc, p, sNN, Nn, nullptr, part, 0, Cc);

    rowsum_kernel<<<(Bb * Nn) / 256, 256>>>(part, rsum);

    // attn: D[n][c] = (E[n,:] . v[c,:]) / rowsum[n] -> bf16 [N,C]
    gemm_mma<5><<<dim3(Cc / TILE_N, Nn / TILE_M, Bb), 256, GEMM_SMEM>>>(
        p, sNN, Nn, v, sCN, Nn, attn, sNC, Cc, nullptr, rsum, Nn, Nn);
    // out: D[o][n] = wo[o,:] . attn[n,:] + bo + x -> fp32 [C,N]
    gemm_mma<4><<<dim3(Nn / TILE_N, Cc / TILE_M, Bb), 256, GEMM_SMEM>>>(
        bwo, 0, Cc, attn, sNC, Cc, out, sCN, Nn, bo, x, sCN, Cc);
}